// round 15
// baseline (speedup 1.0000x reference)
#include <cuda_runtime.h>
#include <cstddef>

// Ghost-cell padding with affine boundary conditions.
// arr: (4, 4096, 4096) f32 -> out: (4, 4098, 4098) f32
//
// Round-15: single-variable retest of the phase-2 READ path only.
// R12 bundled LDS.128 reads WITH a per-row STG.128/STG.64 switch and
// regressed; the implicated mechanism was the store change. Here the global
// store stream is byte-identical to the converged round-6 winner (always
// 2x 8B-aligned STG.64 float2), and only the smem read path changes:
// one aligned LDS.128 + one scalar LDS.32 per 4 outputs instead of 8 scalar
// LDS.32 with 2x duplicate reads. Smem read traffic 2.0x -> 1.25x, LDS
// count /4, targeting the 60% L1 utilization. Everything else (2 rows/CTA,
// 32 KB burst structure, 512 thr, streaming hints) unchanged.

static constexpr int F  = 4;
static constexpr int NX = 4096;
static constexpr int NY = 4096;
static constexpr int PX = NX + 2;   // 4098
static constexpr int PY = NY + 2;   // 4098

static constexpr int THREADS = 512;
static constexpr int RPB     = 2;   // padded rows per block; 4098 = 2 * 2049

__global__ void __launch_bounds__(THREADS, 4)
ghost_pad_kernel(const float* __restrict__ arr,
                 const float* __restrict__ bc,   // bc_const  flat [axis*2+side]
                 const float* __restrict__ bf,   // bc_factor flat [axis*2+side]
                 float* __restrict__ out)
{
    __shared__ float s[RPB][NY];    // staged input rows (32 KB)

    const int row0 = blockIdx.x * RPB;   // first padded row of this block
    const int f    = blockIdx.y;         // field
    const int t    = threadIdx.x;

    // Phase 1: stage RPB source rows into smem, aligned 16B streaming loads.
    #pragma unroll
    for (int rr = 0; rr < RPB; rr++) {
        const int row = row0 + rr;
        const int src = (row == 0) ? 0 : ((row == PX - 1) ? (NX - 1) : (row - 1));
        const float* __restrict__ a = arr + ((size_t)f * NX + src) * NY;
        #pragma unroll
        for (int i = 0; i < 2; i++) {
            const int k = 4 * (t + i * THREADS);          // 0..4092, mult of 4
            *reinterpret_cast<float4*>(&s[rr][k]) =
                __ldcs(reinterpret_cast<const float4*>(a + k));
        }
    }
    __syncthreads();

    // Phase 2: 4 outputs per thread-group; one LDS.128 + one LDS.32 per group.
    // Store path identical to the converged round-6 kernel: 2x STG.64.
    #pragma unroll
    for (int rr = 0; rr < RPB; rr++) {
        const int row = row0 + rr;

        float fac, c, edgeL, edgeR;
        if (row == 0) {
            c = bc[0]; fac = bf[0];                       // top ghost row
            edgeL = 0.0f; edgeR = 0.0f;
        } else if (row == PX - 1) {
            c = bc[1]; fac = bf[1];                       // bottom ghost row
            edgeL = 0.0f; edgeR = 0.0f;
        } else {
            c = 0.0f; fac = 1.0f;                         // fma(1,x,0) == x
            edgeL = fmaf(bf[2], s[rr][0],      bc[2]);
            edgeR = fmaf(bf[3], s[rr][NY - 1], bc[3]);
        }

        // Row base offset = (f*PX + row) * 4098 -> always even,
        // so float2 stores at even offsets are 8B-aligned.
        float* __restrict__ orow = out + ((size_t)f * PX + row) * PY;

        #pragma unroll
        for (int g = 0; g < 2; g++) {
            const int P = 4 * (t + g * THREADS);          // 0..4092, mult of 4
            // Outputs P..P+3 need inputs s[P-1], s[P], s[P+1], s[P+2].
            const float4 v = *reinterpret_cast<const float4*>(&s[rr][P]);
            const float prev = s[rr][(P == 0) ? 0 : (P - 1)];

            float o0 = fmaf(fac, prev, c);
            if (P == 0) o0 = edgeL;                       // single thread
            const float o1 = fmaf(fac, v.x, c);
            const float o2 = fmaf(fac, v.y, c);
            const float o3 = fmaf(fac, v.z, c);

            __stcs(reinterpret_cast<float2*>(orow + P),     make_float2(o0, o1));
            __stcs(reinterpret_cast<float2*>(orow + P + 2), make_float2(o2, o3));
        }

        // Tail pair: positions 4096 (from s[4095]) and 4097 (right edge).
        if (t == 0) {
            __stcs(reinterpret_cast<float2*>(orow + (PY - 2)),
                   make_float2(fmaf(fac, s[rr][NY - 1], c), edgeR));
        }
    }
}

extern "C" void kernel_launch(void* const* d_in, const int* in_sizes, int n_in,
                              void* d_out, int out_size)
{
    const float* arr       = (const float*)d_in[0];
    const float* bc_const  = (const float*)d_in[1];
    const float* bc_factor = (const float*)d_in[2];
    float* out             = (float*)d_out;

    dim3 grid(PX / RPB, F);         // 2049 x 4
    ghost_pad_kernel<<<grid, THREADS>>>(arr, bc_const, bc_factor, out);
}

// round 16
// speedup vs baseline: 1.0817x; 1.0817x over previous
#include <cuda_runtime.h>
#include <cstddef>

// Ghost-cell padding with affine boundary conditions — FINAL (converged,
// reproduced 4x at 82.0±0.1 us).
// arr: (4, 4096, 4096) f32 -> out: (4, 4098, 4098) f32
//
// Converged structure (~7.0 TB/s combined r+w, 79% of HBM spec — the
// read<->write turnaround-limited roofline for this 50/50 stream):
//   - 2 padded rows per CTA staged in 32 KB smem: 32 KB aligned-LDG.128 read
//     burst -> one barrier -> 32 KB STG.64 write burst. The 16->32 KB burst
//     coarsening was the single real win (DRAM 73% -> 79%); 48 KB regresses.
//   - INTERLEAVED pair distribution in phase 2 (thread t stores pair j=2t):
//     each warp STG.64 covers a dense 256B span. Per-thread-contiguous
//     layouts (R12/R15) stride the warp store 16B/lane -> 2x store
//     wavefronts -> regression. This distribution is load-bearing.
//   - 512 threads x 4 CTAs/SM = 2048 threads/SM (max per-SM MLP).
//   - Streaming cache hints (touch-once 537 MB vs 126 MB L2).
//   - Unified row model: orow[p] = fma(fac, a[p-1], c), (fac,c)=(1,0) exact
//     for interior copy rows, bc[axis0,side] for top/bottom ghost rows;
//     edges/corners overridden at j==0 and j==PY-1.
//
// Falsified (single-variable each): shfl realign, register staging,
// persistent CTAs, RPB=1/3, 256/1024-thread blocks, LDS.128 reads,
// STG.128 stores, per-thread-contiguous layouts, cache-hint removal.

static constexpr int F  = 4;
static constexpr int NX = 4096;
static constexpr int NY = 4096;
static constexpr int PX = NX + 2;   // 4098
static constexpr int PY = NY + 2;   // 4098

static constexpr int THREADS = 512;
static constexpr int RPB     = 2;   // padded rows per block; 4098 = 2 * 2049

__global__ void __launch_bounds__(THREADS)
ghost_pad_kernel(const float* __restrict__ arr,
                 const float* __restrict__ bc,   // bc_const  flat [axis*2+side]
                 const float* __restrict__ bf,   // bc_factor flat [axis*2+side]
                 float* __restrict__ out)
{
    __shared__ float s[RPB][NY];    // staged input rows (32 KB)

    const int row0 = blockIdx.x * RPB;   // first padded row of this block
    const int f    = blockIdx.y;         // field
    const int t    = threadIdx.x;

    // Phase 1: stage RPB source rows into smem, aligned 16B streaming loads.
    #pragma unroll
    for (int rr = 0; rr < RPB; rr++) {
        const int row = row0 + rr;
        const int src = (row == 0) ? 0 : ((row == PX - 1) ? (NX - 1) : (row - 1));
        const float* __restrict__ a = arr + ((size_t)f * NX + src) * NY;
        #pragma unroll
        for (int i = 0; i < 2; i++) {
            const int k = 4 * (t + i * THREADS);          // 0..4092, mult of 4
            *reinterpret_cast<float4*>(&s[rr][k]) =
                __ldcs(reinterpret_cast<const float4*>(a + k));
        }
    }
    __syncthreads();

    // Phase 2: per row, shifted read from smem + dense interleaved STG.64.
    #pragma unroll
    for (int rr = 0; rr < RPB; rr++) {
        const int row = row0 + rr;

        float fac, c, edgeL, edgeR;
        if (row == 0) {
            c = bc[0]; fac = bf[0];                       // top ghost row
            edgeL = 0.0f; edgeR = 0.0f;
        } else if (row == PX - 1) {
            c = bc[1]; fac = bf[1];                       // bottom ghost row
            edgeL = 0.0f; edgeR = 0.0f;
        } else {
            c = 0.0f; fac = 1.0f;                         // fma(1,x,0) == x
            edgeL = fmaf(bf[2], s[rr][0],      bc[2]);
            edgeR = fmaf(bf[3], s[rr][NY - 1], bc[3]);
        }

        // Row base offset = (f*PX + row) * 4098 -> always even,
        // so float2 stores at even j are 8B-aligned.
        float* __restrict__ orow = out + ((size_t)f * PX + row) * PY;

        #pragma unroll
        for (int i = 0; i < 4; i++) {
            const int j = 2 * (t + i * THREADS);          // 0..4094, even
            const float l0 = s[rr][(j == 0) ? 0 : (j - 1)];
            const float l1 = s[rr][j];
            float v0 = fmaf(fac, l0, c);
            if (j == 0) v0 = edgeL;                       // single thread
            const float v1 = fmaf(fac, l1, c);
            __stcs(reinterpret_cast<float2*>(orow + j), make_float2(v0, v1));
        }

        // Tail pair: positions 4096 (from a[4095]) and 4097 (right edge).
        if (t == 0) {
            __stcs(reinterpret_cast<float2*>(orow + (PY - 2)),
                   make_float2(fmaf(fac, s[rr][NY - 1], c), edgeR));
        }
    }
}

extern "C" void kernel_launch(void* const* d_in, const int* in_sizes, int n_in,
                              void* d_out, int out_size)
{
    const float* arr       = (const float*)d_in[0];
    const float* bc_const  = (const float*)d_in[1];
    const float* bc_factor = (const float*)d_in[2];
    float* out             = (float*)d_out;

    dim3 grid(PX / RPB, F);         // 2049 x 4
    ghost_pad_kernel<<<grid, THREADS>>>(arr, bc_const, bc_factor, out);
}